// round 2
// baseline (speedup 1.0000x reference)
#include <cuda_runtime.h>
#include <math.h>
#include <float.h>

// ---------------------------------------------------------------------------
// Scratch (no cudaMalloc allowed): device globals.
// ---------------------------------------------------------------------------
__device__ float g_act1[32 * 128 * 128 * 128];  // 256 MB: conv1 out [32,128,128,128]
__device__ float g_act2[32 * 256 * 64 * 64];    // 128 MB: conv2 out [32,256,64,64]
__device__ float g_act3[32 * 256 * 32 * 32];    //  32 MB: conv3 out [32,256,32,32]
__device__ float g_act4[32 * 256 * 16 * 16];    //   8 MB: conv4 out (z) [32,256,16,16]
__device__ float g_cnorm[8192];
__device__ int   g_vqidx[8192];
__device__ float g_lpart[1024];

__device__ __forceinline__ float silu_f(float v) {
    return v / (1.0f + expf(-v));
}

// ---------------------------------------------------------------------------
// Implicit-GEMM conv 4x4 stride2 pad1 + SiLU, fp32.
// Block tile: 128 output channels x 128 output pixels. 256 threads, 8x8 regs.
// K loop over cin; per cin the 16 taps are staged:
//   sA[tap][oc]  = w[ocBase+oc][cin][tap]
//   sB[tap][px]  = x[b][cin][2*oh+kh-1][2*ow+kw-1]  (0 outside)
// Requires Cout % 128 == 0 and (Hout*Wout) % 128 == 0 (true for all 4 layers).
// ---------------------------------------------------------------------------
__global__ __launch_bounds__(256, 2)
void conv_silu_kernel(const float* __restrict__ x, const float* __restrict__ w,
                      const float* __restrict__ bias, float* __restrict__ y,
                      int Cin, int Cout, int Hin, int Win, int Hout, int Wout)
{
    __shared__ float sA[16][128];
    __shared__ float sB[16][128];

    const int t  = threadIdx.x;
    const int tx = t & 15;        // pixel group
    const int ty = t >> 4;        // oc group
    const int pxBase = blockIdx.x * 128;
    const int ocBase = blockIdx.y * 128;
    const int b = blockIdx.z;

    // staging coords for B
    const int p_loc   = t & 127;
    const int tapHalf = t >> 7;   // 0 -> even taps, 1 -> odd taps
    const int p_glob  = pxBase + p_loc;
    const int oh = p_glob / Wout;
    const int ow = p_glob - oh * Wout;
    const int ih0 = 2 * oh - 1;
    const int iw0 = 2 * ow - 1;

    float acc[8][8];
#pragma unroll
    for (int i = 0; i < 8; ++i)
#pragma unroll
        for (int j = 0; j < 8; ++j) acc[i][j] = 0.0f;

    const float* xb = x + (size_t)b * Cin * Hin * Win;

    for (int cin = 0; cin < Cin; ++cin) {
        // ---- stage weights: 512 float4, 2 per thread ----
#pragma unroll
        for (int j = 0; j < 2; ++j) {
            int f  = t * 2 + j;
            int oc = f >> 2;
            int t4 = (f & 3) << 2;
            const float4 v = *reinterpret_cast<const float4*>(
                w + (((size_t)(ocBase + oc) * Cin + cin) << 4) + t4);
            sA[t4 + 0][oc] = v.x;
            sA[t4 + 1][oc] = v.y;
            sA[t4 + 2][oc] = v.z;
            sA[t4 + 3][oc] = v.w;
        }
        // ---- stage im2col gather: 8 taps per thread ----
        {
            const float* xc = xb + (size_t)cin * Hin * Win;
#pragma unroll
            for (int i = 0; i < 8; ++i) {
                int tap = 2 * i + tapHalf;
                int kh = tap >> 2, kw = tap & 3;
                int ih = ih0 + kh;
                int iw = iw0 + kw;
                float v = 0.0f;
                if ((unsigned)ih < (unsigned)Hin && (unsigned)iw < (unsigned)Win)
                    v = xc[ih * Win + iw];
                sB[tap][p_loc] = v;
            }
        }
        __syncthreads();

#pragma unroll
        for (int kk = 0; kk < 16; ++kk) {
            float4 a0 = *reinterpret_cast<const float4*>(&sA[kk][ty * 4]);
            float4 a1 = *reinterpret_cast<const float4*>(&sA[kk][64 + ty * 4]);
            float4 b0 = *reinterpret_cast<const float4*>(&sB[kk][tx * 4]);
            float4 b1 = *reinterpret_cast<const float4*>(&sB[kk][64 + tx * 4]);
            float ar[8] = {a0.x, a0.y, a0.z, a0.w, a1.x, a1.y, a1.z, a1.w};
            float br[8] = {b0.x, b0.y, b0.z, b0.w, b1.x, b1.y, b1.z, b1.w};
#pragma unroll
            for (int i = 0; i < 8; ++i)
#pragma unroll
                for (int j = 0; j < 8; ++j)
                    acc[i][j] += ar[i] * br[j];
        }
        __syncthreads();
    }

    // ---- epilogue: bias + SiLU, float4 stores (px tile is contiguous NCHW) ----
    const int hw = Hout * Wout;
#pragma unroll
    for (int i = 0; i < 8; ++i) {
        int ocl = (i < 4) ? (ty * 4 + i) : (64 + ty * 4 + (i - 4));
        int oc  = ocBase + ocl;
        float bv = bias[oc];
        float* yo = y + (size_t)(b * Cout + oc) * hw + pxBase;
        float4 o0, o1;
        o0.x = silu_f(acc[i][0] + bv);
        o0.y = silu_f(acc[i][1] + bv);
        o0.z = silu_f(acc[i][2] + bv);
        o0.w = silu_f(acc[i][3] + bv);
        o1.x = silu_f(acc[i][4] + bv);
        o1.y = silu_f(acc[i][5] + bv);
        o1.z = silu_f(acc[i][6] + bv);
        o1.w = silu_f(acc[i][7] + bv);
        *reinterpret_cast<float4*>(yo + tx * 4)      = o0;
        *reinterpret_cast<float4*>(yo + 64 + tx * 4) = o1;
    }
}

// ---------------------------------------------------------------------------
// codebook squared norms: one warp per code
// ---------------------------------------------------------------------------
__global__ void cnorm_kernel(const float* __restrict__ cb, float* __restrict__ cn)
{
    int gwarp = (blockIdx.x * blockDim.x + threadIdx.x) >> 5;
    int lane  = threadIdx.x & 31;
    if (gwarp >= 8192) return;
    const float* p = cb + (size_t)gwarp * 256;
    float s = 0.0f;
#pragma unroll
    for (int i = 0; i < 8; ++i) {
        float v = p[lane + 32 * i];
        s += v * v;
    }
#pragma unroll
    for (int o = 16; o > 0; o >>= 1) s += __shfl_xor_sync(0xFFFFFFFFu, s, o);
    if (lane == 0) cn[gwarp] = s;
}

// ---------------------------------------------------------------------------
// Fused VQ: distances + argmin (first-occurrence) + gather + index write.
// Block = 64 z-rows (quarter image). Loops 32 code tiles of 256 codes.
// GEMM: 64x256 tile, K=256 in chunks of 16, 8x8 per thread (32 tx x 8 ty).
// d2 replicates jax op order: (|z|^2 - 2*dot) + |c|^2, no FMA contraction.
// ---------------------------------------------------------------------------
__global__ __launch_bounds__(256)
void vq_kernel(const float* __restrict__ z, const float* __restrict__ cb,
               const float* __restrict__ cnorm,
               float* __restrict__ outQ, float* __restrict__ outIdx,
               int* __restrict__ idxOut)
{
    __shared__ float sZ[16][64];
    __shared__ float sC[16][256];
    __shared__ float zn[64];
    __shared__ float zpart[4][64];
    __shared__ float rmv[64][33];
    __shared__ int   rmi[64][33];
    __shared__ int   bidx[64];

    const int t = threadIdx.x;
    const int b = blockIdx.x >> 2;
    const int sBase = (blockIdx.x & 3) << 6;

    // ---- znorm for the 64 rows ----
    {
        int j = t & 63, dg = t >> 6;   // 4 dim-groups of 64
        const float* zp = z + ((size_t)(b * 256 + dg * 64) << 8) + sBase + j;
        float s = 0.0f;
        for (int d = 0; d < 64; ++d) {
            float v = zp[(size_t)d << 8];
            s += v * v;
        }
        zpart[dg][j] = s;
    }
    __syncthreads();
    if (t < 64) zn[t] = ((zpart[0][t] + zpart[1][t]) + zpart[2][t]) + zpart[3][t];
    __syncthreads();

    const int tx = t & 31;   // code groups
    const int ty = t >> 5;   // row groups (8)

    int   rl[8];
#pragma unroll
    for (int i = 0; i < 4; ++i) { rl[i] = ty * 4 + i; rl[4 + i] = 32 + ty * 4 + i; }
    float znr[8];
#pragma unroll
    for (int i = 0; i < 8; ++i) znr[i] = zn[rl[i]];

    float minv[8];
    int   mini[8];
#pragma unroll
    for (int i = 0; i < 8; ++i) { minv[i] = FLT_MAX; mini[i] = 0; }

    for (int ct = 0; ct < 32; ++ct) {
        float dot[8][8];
#pragma unroll
        for (int i = 0; i < 8; ++i)
#pragma unroll
            for (int j = 0; j < 8; ++j) dot[i][j] = 0.0f;

        for (int kc = 0; kc < 16; ++kc) {
            // stage z chunk [16 dims][64 rows], coalesced float4
            {
                int dd = t >> 4, j4 = (t & 15) << 2;
                float4 v = *reinterpret_cast<const float4*>(
                    z + ((size_t)(b * 256 + kc * 16 + dd) << 8) + sBase + j4);
                *reinterpret_cast<float4*>(&sZ[dd][j4]) = v;
            }
            // stage codebook chunk [16 dims][256 codes]
#pragma unroll
            for (int i2 = 0; i2 < 4; ++i2) {
                int f  = t + (i2 << 8);
                int cl = f >> 2;
                int dq = (f & 3) << 2;
                float4 v = *reinterpret_cast<const float4*>(
                    cb + ((size_t)(ct * 256 + cl) << 8) + kc * 16 + dq);
                sC[dq + 0][cl] = v.x;
                sC[dq + 1][cl] = v.y;
                sC[dq + 2][cl] = v.z;
                sC[dq + 3][cl] = v.w;
            }
            __syncthreads();
#pragma unroll
            for (int kk = 0; kk < 16; ++kk) {
                float4 a0 = *reinterpret_cast<const float4*>(&sZ[kk][ty * 4]);
                float4 a1 = *reinterpret_cast<const float4*>(&sZ[kk][32 + ty * 4]);
                float4 b0 = *reinterpret_cast<const float4*>(&sC[kk][tx * 4]);
                float4 b1 = *reinterpret_cast<const float4*>(&sC[kk][128 + tx * 4]);
                float ar[8] = {a0.x, a0.y, a0.z, a0.w, a1.x, a1.y, a1.z, a1.w};
                float br[8] = {b0.x, b0.y, b0.z, b0.w, b1.x, b1.y, b1.z, b1.w};
#pragma unroll
                for (int i = 0; i < 8; ++i)
#pragma unroll
                    for (int j = 0; j < 8; ++j)
                        dot[i][j] += ar[i] * br[j];
            }
            __syncthreads();
        }

        // epilogue: distances + running argmin (ascending code order)
        const int cbase = ct << 8;
#pragma unroll
        for (int j = 0; j < 8; ++j) {
            int code = cbase + ((j < 4) ? (tx * 4 + j) : (128 + tx * 4 + (j - 4)));
            float cn = cnorm[code];
#pragma unroll
            for (int i = 0; i < 8; ++i) {
                float d2 = __fadd_rn(__fsub_rn(znr[i], __fmul_rn(2.0f, dot[i][j])), cn);
                if (d2 < minv[i]) { minv[i] = d2; mini[i] = code; }
            }
        }
    }

    // cross-thread reduce per row (ties -> lowest code index, matching jnp.argmin)
#pragma unroll
    for (int i = 0; i < 8; ++i) { rmv[rl[i]][tx] = minv[i]; rmi[rl[i]][tx] = mini[i]; }
    __syncthreads();
    if (t < 64) {
        float bv = rmv[t][0];
        int   bi = rmi[t][0];
        for (int x2 = 1; x2 < 32; ++x2) {
            float v = rmv[t][x2];
            int   ii = rmi[t][x2];
            if (v < bv || (v == bv && ii < bi)) { bv = v; bi = ii; }
        }
        bidx[t] = bi;
        int r = (b << 8) + sBase + t;
        outIdx[r] = (float)bi;
        idxOut[r] = bi;
    }
    __syncthreads();

    // gather quantized into [B, D, 16, 16] layout (coalesced over s)
    for (int i2 = 0; i2 < 64; ++i2) {
        int g = (i2 << 8) + t;      // 16384 elems per block
        int d = g >> 6;
        int j = g & 63;
        outQ[((size_t)(b * 256 + d) << 8) + sBase + j] = cb[((size_t)bidx[j] << 8) + d];
    }
}

// ---------------------------------------------------------------------------
// commit loss: deterministic two-stage reduction (no atomics -> graph-replay
// bit-stable). N = 2^21, mean multiply is exact (1/2^21).
// ---------------------------------------------------------------------------
__global__ void loss_partial_kernel(const float* __restrict__ z, const float* __restrict__ cb,
                                    const int* __restrict__ idx, float* __restrict__ part)
{
    __shared__ float sm[256];
    const int t = threadIdx.x;
    float s = 0.0f;
    for (int n = blockIdx.x * 256 + t; n < 32 * 256 * 256; n += 1024 * 256) {
        int b    = n >> 16;
        int rem  = n & 65535;
        int d    = rem >> 8;
        int sPos = n & 255;
        int r    = (b << 8) + sPos;
        float q  = cb[((size_t)idx[r] << 8) + d];
        float diff = z[n] - q;
        s += diff * diff;
    }
    sm[t] = s;
    __syncthreads();
    for (int o = 128; o > 0; o >>= 1) {
        if (t < o) sm[t] += sm[t + o];
        __syncthreads();
    }
    if (t == 0) part[blockIdx.x] = sm[0];
}

__global__ void loss_final_kernel(const float* __restrict__ part, float* __restrict__ out)
{
    __shared__ float sm[256];
    const int t = threadIdx.x;
    sm[t] = ((part[t] + part[t + 256]) + part[t + 512]) + part[t + 768];
    __syncthreads();
    for (int o = 128; o > 0; o >>= 1) {
        if (t < o) sm[t] += sm[t + o];
        __syncthreads();
    }
    if (t == 0) out[0] = sm[0] * (1.0f / 2097152.0f);
}

// ---------------------------------------------------------------------------
// launch
// Inputs: images, w1,b1, w2,b2, w3,b3, w4,b4, codebook
// Output (float32): quantized [32,256,16,16] (2097152) | indices [32,256] (8192) | loss (1)
// ---------------------------------------------------------------------------
extern "C" void kernel_launch(void* const* d_in, const int* in_sizes, int n_in,
                              void* d_out, int out_size)
{
    const float* images = (const float*)d_in[0];
    const float* w1 = (const float*)d_in[1];
    const float* b1 = (const float*)d_in[2];
    const float* w2 = (const float*)d_in[3];
    const float* b2 = (const float*)d_in[4];
    const float* w3 = (const float*)d_in[5];
    const float* b3 = (const float*)d_in[6];
    const float* w4 = (const float*)d_in[7];
    const float* b4 = (const float*)d_in[8];
    const float* cb = (const float*)d_in[9];

    float *a1, *a2, *a3, *a4, *cn, *lp;
    int* vidx;
    cudaGetSymbolAddress((void**)&a1, g_act1);
    cudaGetSymbolAddress((void**)&a2, g_act2);
    cudaGetSymbolAddress((void**)&a3, g_act3);
    cudaGetSymbolAddress((void**)&a4, g_act4);
    cudaGetSymbolAddress((void**)&cn, g_cnorm);
    cudaGetSymbolAddress((void**)&lp, g_lpart);
    cudaGetSymbolAddress((void**)&vidx, g_vqidx);

    float* out     = (float*)d_out;
    float* outQ    = out;
    float* outIdx  = out + 2097152;
    float* outLoss = out + 2105344;

    // Encoder: 256 -> 128 -> 64 -> 32 -> 16
    conv_silu_kernel<<<dim3(128, 1, 32), 256>>>(images, w1, b1, a1, 3,   128, 256, 256, 128, 128);
    conv_silu_kernel<<<dim3(32,  2, 32), 256>>>(a1,     w2, b2, a2, 128, 256, 128, 128, 64,  64);
    conv_silu_kernel<<<dim3(8,   2, 32), 256>>>(a2,     w3, b3, a3, 256, 256, 64,  64,  32,  32);
    conv_silu_kernel<<<dim3(2,   2, 32), 256>>>(a3,     w4, b4, a4, 256, 256, 32,  32,  16,  16);

    // VQ
    cnorm_kernel<<<1024, 256>>>(cb, cn);
    vq_kernel<<<128, 256>>>(a4, cb, cn, outQ, outIdx, vidx);

    // commit loss
    loss_partial_kernel<<<1024, 256>>>(a4, cb, vidx, lp);
    loss_final_kernel<<<1, 256>>>(lp, outLoss);
}

// round 3
// speedup vs baseline: 1.1465x; 1.1465x over previous
#include <cuda_runtime.h>
#include <math.h>
#include <float.h>

typedef unsigned long long ull;

// ---------------------------------------------------------------------------
// Scratch (no cudaMalloc allowed): device globals.
// ---------------------------------------------------------------------------
__device__ float g_act1[32 * 128 * 128 * 128];  // 256 MB: conv1 out
__device__ float g_act2[32 * 256 * 64 * 64];    // 128 MB: conv2 out
__device__ float g_act3[32 * 256 * 32 * 32];    //  32 MB: conv3 out
__device__ float g_act4[32 * 256 * 16 * 16];    //   8 MB: conv4 out (z)
__device__ float g_cnorm[8192];
__device__ int   g_vqidx[8192];
__device__ float g_lpart[1024];
// transposed weights: wT[(cin*16+tap)*Cout + oc]
__device__ float g_w1T[128 * 3 * 16];
__device__ float g_w2T[256 * 128 * 16];
__device__ float g_w3T[256 * 256 * 16];
__device__ float g_w4T[256 * 256 * 16];

__device__ __forceinline__ float silu_f(float v) {
    return v / (1.0f + expf(-v));
}

// ---- packed fp32x2 FMA (full-rate FP32 path on sm_100) ----
__device__ __forceinline__ ull fma2(ull a, ull b, ull c) {
    ull d;
    asm("fma.rn.f32x2 %0, %1, %2, %3;" : "=l"(d) : "l"(a), "l"(b), "l"(c));
    return d;
}
__device__ __forceinline__ ull pack2(float x, float y) {
    ull d;
    asm("mov.b64 %0, {%1, %2};" : "=l"(d) : "f"(x), "f"(y));
    return d;
}
__device__ __forceinline__ float2 unpack2(ull v) {
    float2 r;
    asm("mov.b64 {%0, %1}, %2;" : "=f"(r.x), "=f"(r.y) : "l"(v));
    return r;
}

// ---- cp.async helpers ----
__device__ __forceinline__ void cp16(void* smem_dst, const void* gsrc) {
    unsigned s = (unsigned)__cvta_generic_to_shared(smem_dst);
    asm volatile("cp.async.cg.shared.global [%0], [%1], 16;" :: "r"(s), "l"(gsrc) : "memory");
}
__device__ __forceinline__ void cp4z(void* smem_dst, const void* gsrc, int src_size) {
    unsigned s = (unsigned)__cvta_generic_to_shared(smem_dst);
    asm volatile("cp.async.ca.shared.global [%0], [%1], 4, %2;"
                 :: "r"(s), "l"(gsrc), "r"(src_size) : "memory");
}
__device__ __forceinline__ void cp_commit() {
    asm volatile("cp.async.commit_group;" ::: "memory");
}
template <int N>
__device__ __forceinline__ void cp_wait() {
    asm volatile("cp.async.wait_group %0;" :: "n"(N) : "memory");
}

// ---------------------------------------------------------------------------
// Weight transpose: w[oc][cin][tap] -> wT[(cin*16+tap)*Cout + oc]
// ---------------------------------------------------------------------------
__global__ void wtrans_kernel(const float* __restrict__ w, float* __restrict__ wT,
                              int Cin, int Cout)
{
    int n = Cout * Cin * 16;
    int o = blockIdx.x * blockDim.x + threadIdx.x;
    if (o >= n) return;
    int oc  = o % Cout;
    int r   = o / Cout;
    int cin = r >> 4;
    int tap = r & 15;
    wT[o] = w[((size_t)(oc * Cin + cin) << 4) + tap];
}

// ---------------------------------------------------------------------------
// Implicit-GEMM conv 4x4 stride2 pad1 + SiLU, fp32, f32x2 inner product,
// cp.async double-buffered over cin.
// Block tile: 128 oc x 128 px. 256 threads, 8x8 regs (as 8x4 f32x2 pairs).
// ---------------------------------------------------------------------------
__global__ __launch_bounds__(256, 2)
void conv_silu_kernel(const float* __restrict__ x, const float* __restrict__ wT,
                      const float* __restrict__ bias, float* __restrict__ y,
                      int Cin, int Cout, int Hin, int Win, int Hout, int Wout)
{
    __shared__ float sA[2][16][128];
    __shared__ float sB[2][16][128];

    const int t  = threadIdx.x;
    const int tx = t & 15;        // pixel group
    const int ty = t >> 4;        // oc group
    const int pxBase = blockIdx.x * 128;
    const int ocBase = blockIdx.y * 128;
    const int b = blockIdx.z;

    // staging coords for B
    const int p_loc   = t & 127;
    const int tapHalf = t >> 7;   // 0 -> even taps, 1 -> odd taps
    const int p_glob  = pxBase + p_loc;
    const int oh = p_glob / Wout;
    const int ow = p_glob - oh * Wout;
    const int ih0 = 2 * oh - 1;
    const int iw0 = 2 * ow - 1;

    const float* xb = x + (size_t)b * Cin * Hin * Win;

    ull accp[8][4];
#pragma unroll
    for (int i = 0; i < 8; ++i)
#pragma unroll
        for (int j = 0; j < 4; ++j) accp[i][j] = 0ull;

    // stage one cin slice into buffer `buf`
    auto stage = [&](int buf, int cin) {
        // A: 16x128 floats = 512 float4; 2 per thread (contiguous thanks to wT)
#pragma unroll
        for (int j = 0; j < 2; ++j) {
            int f   = t * 2 + j;
            int tap = f >> 5;
            int c4  = f & 31;
            const float* src = wT + ((size_t)(cin * 16 + tap) * Cout + ocBase + c4 * 4);
            cp16(&sA[buf][tap][c4 * 4], src);
        }
        // B: 8 taps per thread, 4B zfill copies
        const float* xc = xb + (size_t)cin * Hin * Win;
#pragma unroll
        for (int i = 0; i < 8; ++i) {
            int tap = 2 * i + tapHalf;
            int kh = tap >> 2, kw = tap & 3;
            int ih = ih0 + kh;
            int iw = iw0 + kw;
            bool ok = (unsigned)ih < (unsigned)Hin && (unsigned)iw < (unsigned)Win;
            const float* src = ok ? (xc + ih * Win + iw) : xc;
            cp4z(&sB[buf][tap][p_loc], src, ok ? 4 : 0);
        }
    };

    stage(0, 0);
    cp_commit();

    for (int cin = 0; cin < Cin; ++cin) {
        const int buf = cin & 1;
        if (cin + 1 < Cin) {
            stage(buf ^ 1, cin + 1);
            cp_commit();
            cp_wait<1>();
        } else {
            cp_wait<0>();
        }
        __syncthreads();

#pragma unroll
        for (int kk = 0; kk < 16; ++kk) {
            float4 a0 = *reinterpret_cast<const float4*>(&sA[buf][kk][ty * 4]);
            float4 a1 = *reinterpret_cast<const float4*>(&sA[buf][kk][64 + ty * 4]);
            ulonglong2 bq0 = *reinterpret_cast<const ulonglong2*>(&sB[buf][kk][tx * 4]);
            ulonglong2 bq1 = *reinterpret_cast<const ulonglong2*>(&sB[buf][kk][64 + tx * 4]);
            ull bp[4] = {bq0.x, bq0.y, bq1.x, bq1.y};
            float ar[8] = {a0.x, a0.y, a0.z, a0.w, a1.x, a1.y, a1.z, a1.w};
#pragma unroll
            for (int i = 0; i < 8; ++i) {
                ull ad = pack2(ar[i], ar[i]);
#pragma unroll
                for (int jp = 0; jp < 4; ++jp)
                    accp[i][jp] = fma2(ad, bp[jp], accp[i][jp]);
            }
        }
        __syncthreads();
    }

    // ---- epilogue: bias + SiLU, float4 stores ----
    const int hw = Hout * Wout;
#pragma unroll
    for (int i = 0; i < 8; ++i) {
        int ocl = (i < 4) ? (ty * 4 + i) : (64 + ty * 4 + (i - 4));
        int oc  = ocBase + ocl;
        float bv = bias[oc];
        float* yo = y + (size_t)(b * Cout + oc) * hw + pxBase;
        float2 p0 = unpack2(accp[i][0]);
        float2 p1 = unpack2(accp[i][1]);
        float2 p2 = unpack2(accp[i][2]);
        float2 p3 = unpack2(accp[i][3]);
        float4 o0, o1;
        o0.x = silu_f(p0.x + bv);
        o0.y = silu_f(p0.y + bv);
        o0.z = silu_f(p1.x + bv);
        o0.w = silu_f(p1.y + bv);
        o1.x = silu_f(p2.x + bv);
        o1.y = silu_f(p2.y + bv);
        o1.z = silu_f(p3.x + bv);
        o1.w = silu_f(p3.y + bv);
        *reinterpret_cast<float4*>(yo + tx * 4)      = o0;
        *reinterpret_cast<float4*>(yo + 64 + tx * 4) = o1;
    }
}

// ---------------------------------------------------------------------------
// codebook squared norms: one warp per code
// ---------------------------------------------------------------------------
__global__ void cnorm_kernel(const float* __restrict__ cb, float* __restrict__ cn)
{
    int gwarp = (blockIdx.x * blockDim.x + threadIdx.x) >> 5;
    int lane  = threadIdx.x & 31;
    if (gwarp >= 8192) return;
    const float* p = cb + (size_t)gwarp * 256;
    float s = 0.0f;
#pragma unroll
    for (int i = 0; i < 8; ++i) {
        float v = p[lane + 32 * i];
        s += v * v;
    }
#pragma unroll
    for (int o = 16; o > 0; o >>= 1) s += __shfl_xor_sync(0xFFFFFFFFu, s, o);
    if (lane == 0) cn[gwarp] = s;
}

// ---------------------------------------------------------------------------
// Fused VQ: distances + argmin (first-occurrence) + gather + index write.
// f32x2 inner product; d2 epilogue keeps exact jax op order / no contraction.
// ---------------------------------------------------------------------------
__global__ __launch_bounds__(256)
void vq_kernel(const float* __restrict__ z, const float* __restrict__ cb,
               const float* __restrict__ cnorm,
               float* __restrict__ outQ, float* __restrict__ outIdx,
               int* __restrict__ idxOut)
{
    __shared__ float sZ[16][64];
    __shared__ float sC[16][256];
    __shared__ float zn[64];
    __shared__ float zpart[4][64];
    __shared__ float rmv[64][33];
    __shared__ int   rmi[64][33];
    __shared__ int   bidx[64];

    const int t = threadIdx.x;
    const int b = blockIdx.x >> 2;
    const int sBase = (blockIdx.x & 3) << 6;

    // ---- znorm for the 64 rows ----
    {
        int j = t & 63, dg = t >> 6;
        const float* zp = z + ((size_t)(b * 256 + dg * 64) << 8) + sBase + j;
        float s = 0.0f;
        for (int d = 0; d < 64; ++d) {
            float v = zp[(size_t)d << 8];
            s += v * v;
        }
        zpart[dg][j] = s;
    }
    __syncthreads();
    if (t < 64) zn[t] = ((zpart[0][t] + zpart[1][t]) + zpart[2][t]) + zpart[3][t];
    __syncthreads();

    const int tx = t & 31;
    const int ty = t >> 5;

    int rl[8];
#pragma unroll
    for (int i = 0; i < 4; ++i) { rl[i] = ty * 4 + i; rl[4 + i] = 32 + ty * 4 + i; }
    float znr[8];
#pragma unroll
    for (int i = 0; i < 8; ++i) znr[i] = zn[rl[i]];

    float minv[8];
    int   mini[8];
#pragma unroll
    for (int i = 0; i < 8; ++i) { minv[i] = FLT_MAX; mini[i] = 0; }

    for (int ct = 0; ct < 32; ++ct) {
        ull dotp[8][4];
#pragma unroll
        for (int i = 0; i < 8; ++i)
#pragma unroll
            for (int j = 0; j < 4; ++j) dotp[i][j] = 0ull;

        for (int kc = 0; kc < 16; ++kc) {
            {
                int dd = t >> 4, j4 = (t & 15) << 2;
                float4 v = *reinterpret_cast<const float4*>(
                    z + ((size_t)(b * 256 + kc * 16 + dd) << 8) + sBase + j4);
                *reinterpret_cast<float4*>(&sZ[dd][j4]) = v;
            }
#pragma unroll
            for (int i2 = 0; i2 < 4; ++i2) {
                int f  = t + (i2 << 8);
                int cl = f >> 2;
                int dq = (f & 3) << 2;
                float4 v = *reinterpret_cast<const float4*>(
                    cb + ((size_t)(ct * 256 + cl) << 8) + kc * 16 + dq);
                sC[dq + 0][cl] = v.x;
                sC[dq + 1][cl] = v.y;
                sC[dq + 2][cl] = v.z;
                sC[dq + 3][cl] = v.w;
            }
            __syncthreads();
#pragma unroll
            for (int kk = 0; kk < 16; ++kk) {
                float4 a0 = *reinterpret_cast<const float4*>(&sZ[kk][ty * 4]);
                float4 a1 = *reinterpret_cast<const float4*>(&sZ[kk][32 + ty * 4]);
                ulonglong2 c0 = *reinterpret_cast<const ulonglong2*>(&sC[kk][tx * 4]);
                ulonglong2 c1 = *reinterpret_cast<const ulonglong2*>(&sC[kk][128 + tx * 4]);
                ull bp[4] = {c0.x, c0.y, c1.x, c1.y};
                float ar[8] = {a0.x, a0.y, a0.z, a0.w, a1.x, a1.y, a1.z, a1.w};
#pragma unroll
                for (int i = 0; i < 8; ++i) {
                    ull ad = pack2(ar[i], ar[i]);
#pragma unroll
                    for (int jp = 0; jp < 4; ++jp)
                        dotp[i][jp] = fma2(ad, bp[jp], dotp[i][jp]);
                }
            }
            __syncthreads();
        }

        // epilogue: distances + running argmin (ascending code order)
        const int cbase = ct << 8;
#pragma unroll
        for (int i = 0; i < 8; ++i) {
            float2 q0 = unpack2(dotp[i][0]);
            float2 q1 = unpack2(dotp[i][1]);
            float2 q2 = unpack2(dotp[i][2]);
            float2 q3 = unpack2(dotp[i][3]);
            float dv[8] = {q0.x, q0.y, q1.x, q1.y, q2.x, q2.y, q3.x, q3.y};
#pragma unroll
            for (int j = 0; j < 8; ++j) {
                int code = cbase + ((j < 4) ? (tx * 4 + j) : (128 + tx * 4 + (j - 4)));
                float cn = cnorm[code];
                float d2 = __fadd_rn(__fsub_rn(znr[i], __fmul_rn(2.0f, dv[j])), cn);
                if (d2 < minv[i]) { minv[i] = d2; mini[i] = code; }
            }
        }
    }

    // cross-thread reduce per row (ties -> lowest code index)
#pragma unroll
    for (int i = 0; i < 8; ++i) { rmv[rl[i]][tx] = minv[i]; rmi[rl[i]][tx] = mini[i]; }
    __syncthreads();
    if (t < 64) {
        float bv = rmv[t][0];
        int   bi = rmi[t][0];
        for (int x2 = 1; x2 < 32; ++x2) {
            float v  = rmv[t][x2];
            int   ii = rmi[t][x2];
            if (v < bv || (v == bv && ii < bi)) { bv = v; bi = ii; }
        }
        bidx[t] = bi;
        int r = (b << 8) + sBase + t;
        outIdx[r] = (float)bi;
        idxOut[r] = bi;
    }
    __syncthreads();

    // gather quantized into [B, D, 16, 16] layout
    for (int i2 = 0; i2 < 64; ++i2) {
        int g = (i2 << 8) + t;
        int d = g >> 6;
        int j = g & 63;
        outQ[((size_t)(b * 256 + d) << 8) + sBase + j] = cb[((size_t)bidx[j] << 8) + d];
    }
}

// ---------------------------------------------------------------------------
// commit loss: deterministic two-stage reduction
// ---------------------------------------------------------------------------
__global__ void loss_partial_kernel(const float* __restrict__ z, const float* __restrict__ cb,
                                    const int* __restrict__ idx, float* __restrict__ part)
{
    __shared__ float sm[256];
    const int t = threadIdx.x;
    float s = 0.0f;
    for (int n = blockIdx.x * 256 + t; n < 32 * 256 * 256; n += 1024 * 256) {
        int b    = n >> 16;
        int rem  = n & 65535;
        int d    = rem >> 8;
        int sPos = n & 255;
        int r    = (b << 8) + sPos;
        float q  = cb[((size_t)idx[r] << 8) + d];
        float diff = z[n] - q;
        s += diff * diff;
        (void)rem;
    }
    sm[t] = s;
    __syncthreads();
    for (int o = 128; o > 0; o >>= 1) {
        if (t < o) sm[t] += sm[t + o];
        __syncthreads();
    }
    if (t == 0) part[blockIdx.x] = sm[0];
}

__global__ void loss_final_kernel(const float* __restrict__ part, float* __restrict__ out)
{
    __shared__ float sm[256];
    const int t = threadIdx.x;
    sm[t] = ((part[t] + part[t + 256]) + part[t + 512]) + part[t + 768];
    __syncthreads();
    for (int o = 128; o > 0; o >>= 1) {
        if (t < o) sm[t] += sm[t + o];
        __syncthreads();
    }
    if (t == 0) out[0] = sm[0] * (1.0f / 2097152.0f);
}

// ---------------------------------------------------------------------------
// launch
// ---------------------------------------------------------------------------
extern "C" void kernel_launch(void* const* d_in, const int* in_sizes, int n_in,
                              void* d_out, int out_size)
{
    const float* images = (const float*)d_in[0];
    const float* w1 = (const float*)d_in[1];
    const float* b1 = (const float*)d_in[2];
    const float* w2 = (const float*)d_in[3];
    const float* b2 = (const float*)d_in[4];
    const float* w3 = (const float*)d_in[5];
    const float* b3 = (const float*)d_in[6];
    const float* w4 = (const float*)d_in[7];
    const float* b4 = (const float*)d_in[8];
    const float* cb = (const float*)d_in[9];

    float *a1, *a2, *a3, *a4, *cn, *lp;
    float *w1T, *w2T, *w3T, *w4T;
    int* vidx;
    cudaGetSymbolAddress((void**)&a1, g_act1);
    cudaGetSymbolAddress((void**)&a2, g_act2);
    cudaGetSymbolAddress((void**)&a3, g_act3);
    cudaGetSymbolAddress((void**)&a4, g_act4);
    cudaGetSymbolAddress((void**)&cn, g_cnorm);
    cudaGetSymbolAddress((void**)&lp, g_lpart);
    cudaGetSymbolAddress((void**)&vidx, g_vqidx);
    cudaGetSymbolAddress((void**)&w1T, g_w1T);
    cudaGetSymbolAddress((void**)&w2T, g_w2T);
    cudaGetSymbolAddress((void**)&w3T, g_w3T);
    cudaGetSymbolAddress((void**)&w4T, g_w4T);

    float* out     = (float*)d_out;
    float* outQ    = out;
    float* outIdx  = out + 2097152;
    float* outLoss = out + 2105344;

    // weight transposes (tiny)
    wtrans_kernel<<<(128 * 3 * 16 + 255) / 256, 256>>>(w1, w1T, 3, 128);
    wtrans_kernel<<<(256 * 128 * 16 + 255) / 256, 256>>>(w2, w2T, 128, 256);
    wtrans_kernel<<<(256 * 256 * 16 + 255) / 256, 256>>>(w3, w3T, 256, 256);
    wtrans_kernel<<<(256 * 256 * 16 + 255) / 256, 256>>>(w4, w4T, 256, 256);

    // Encoder: 256 -> 128 -> 64 -> 32 -> 16
    conv_silu_kernel<<<dim3(128, 1, 32), 256>>>(images, w1T, b1, a1, 3,   128, 256, 256, 128, 128);
    conv_silu_kernel<<<dim3(32,  2, 32), 256>>>(a1,     w2T, b2, a2, 128, 256, 128, 128, 64,  64);
    conv_silu_kernel<<<dim3(8,   2, 32), 256>>>(a2,     w3T, b3, a3, 256, 256, 64,  64,  32,  32);
    conv_silu_kernel<<<dim3(2,   2, 32), 256>>>(a3,     w4T, b4, a4, 256, 256, 32,  32,  16,  16);

    // VQ
    cnorm_kernel<<<1024, 256>>>(cb, cn);
    vq_kernel<<<128, 256>>>(a4, cb, cn, outQ, outIdx, vidx);

    // commit loss
    loss_partial_kernel<<<1024, 256>>>(a4, cb, vidx, lp);
    loss_final_kernel<<<1, 256>>>(lp, outLoss);
}

// round 7
// speedup vs baseline: 1.3758x; 1.2000x over previous
#include <cuda_runtime.h>
#include <cuda_bf16.h>
#include <math.h>
#include <float.h>

typedef unsigned long long ull;
typedef unsigned int u32;

// ---------------------------------------------------------------------------
// Scratch (no cudaMalloc allowed): device globals.
// ---------------------------------------------------------------------------
__device__ u32   g_a1x2[32 * 128 * 128 * 128];  // conv1 out, packed bf16 hi/lo per elem
__device__ u32   g_a2x2[32 * 256 * 64 * 64];    // conv2 out, packed hi/lo
__device__ float g_act3[32 * 256 * 32 * 32];    // conv3 out fp32
__device__ float g_act4[32 * 256 * 16 * 16];    // conv4 out (z) fp32
__device__ float g_cnorm[8192];
__device__ int   g_vqidx[8192];
__device__ float g_lpart[1024];
// fp32-path transposed weights (conv1, conv4): wT[(cin*16+tap)*Cout + oc]
__device__ float g_w1T[128 * 3 * 16];
__device__ float g_w4T[256 * 256 * 16];
// MMA weight blobs (pre-swizzled smem images): [ocb][chunk][mat(2)][8192 bf16]
__device__ __nv_bfloat16 g_w2blob[2 * 64 * 2 * 8192];
__device__ __nv_bfloat16 g_w3blob[2 * 128 * 2 * 8192];

__device__ __forceinline__ float silu_f(float v) { return v / (1.0f + expf(-v)); }

// ---- packed fp32x2 FMA ----
__device__ __forceinline__ ull fma2(ull a, ull b, ull c) {
    ull d; asm("fma.rn.f32x2 %0, %1, %2, %3;" : "=l"(d) : "l"(a), "l"(b), "l"(c)); return d;
}
__device__ __forceinline__ ull pack2(float x, float y) {
    ull d; asm("mov.b64 %0, {%1, %2};" : "=l"(d) : "f"(x), "f"(y)); return d;
}
__device__ __forceinline__ float2 unpack2(ull v) {
    float2 r; asm("mov.b64 {%0, %1}, %2;" : "=f"(r.x), "=f"(r.y) : "l"(v)); return r;
}

// ---- hi/lo bf16 split, packed into u32 (low 16 = hi term, high 16 = lo term)
__device__ __forceinline__ u32 pack_x2(float v) {
    __nv_bfloat16 h = __float2bfloat16(v);
    float hf = __bfloat162float(h);
    __nv_bfloat16 l = __float2bfloat16(v - hf);
    unsigned short hb = __bfloat16_as_ushort(h);
    unsigned short lb = __bfloat16_as_ushort(l);
    return (u32)hb | ((u32)lb << 16);
}

// ---- cp.async helpers ----
__device__ __forceinline__ void cp16(void* smem_dst, const void* gsrc) {
    unsigned s = (unsigned)__cvta_generic_to_shared(smem_dst);
    asm volatile("cp.async.cg.shared.global [%0], [%1], 16;" :: "r"(s), "l"(gsrc) : "memory");
}
__device__ __forceinline__ void cp4z(void* smem_dst, const void* gsrc, int src_size) {
    unsigned s = (unsigned)__cvta_generic_to_shared(smem_dst);
    asm volatile("cp.async.ca.shared.global [%0], [%1], 4, %2;"
                 :: "r"(s), "l"(gsrc), "r"(src_size) : "memory");
}
__device__ __forceinline__ void cp_commit() { asm volatile("cp.async.commit_group;" ::: "memory"); }
template <int N>
__device__ __forceinline__ void cp_wait() { asm volatile("cp.async.wait_group %0;" :: "n"(N) : "memory"); }

__device__ __forceinline__ u32 smem_u32(const void* p) {
    return (u32)__cvta_generic_to_shared(p);
}
__device__ __forceinline__ u32 swz128(u32 byte_off) { return byte_off ^ ((byte_off >> 3) & 0x70); }

// ---- ldmatrix / mma.sync (baseline sm_80 PTX -> valid on target sm_100) ----
__device__ __forceinline__ void ldmatrix_x4(u32& r0, u32& r1, u32& r2, u32& r3, u32 addr) {
    asm volatile("ldmatrix.sync.aligned.m8n8.x4.shared.b16 {%0, %1, %2, %3}, [%4];"
                 : "=r"(r0), "=r"(r1), "=r"(r2), "=r"(r3) : "r"(addr));
}
__device__ __forceinline__ void mma_bf16(float* c, const u32* a, const u32* b) {
    asm volatile("mma.sync.aligned.m16n8k16.row.col.f32.bf16.bf16.f32 "
                 "{%0, %1, %2, %3}, {%4, %5, %6, %7}, {%8, %9}, {%0, %1, %2, %3};"
                 : "+f"(c[0]), "+f"(c[1]), "+f"(c[2]), "+f"(c[3])
                 : "r"(a[0]), "r"(a[1]), "r"(a[2]), "r"(a[3]), "r"(b[0]), "r"(b[1]));
}

// ---------------------------------------------------------------------------
// fp32-path weight transpose (conv1, conv4)
// ---------------------------------------------------------------------------
__global__ void wtrans_kernel(const float* __restrict__ w, float* __restrict__ wT,
                              int Cin, int Cout)
{
    int n = Cout * Cin * 16;
    int o = blockIdx.x * blockDim.x + threadIdx.x;
    if (o >= n) return;
    int oc  = o % Cout;
    int r   = o / Cout;
    int cin = r >> 4;
    int tap = r & 15;
    wT[o] = w[((size_t)(oc * Cin + cin) << 4) + tap];
}

// ---------------------------------------------------------------------------
// MMA weight blob prep: pre-swizzled smem tiles (rows=oc, 64 k2 bf16 = 128B/row).
//   k2 = 64c+q ; k = k2>>1 ; par = k2&1 ; cin = k>>4 ; tap = k&15 ; oc = 128*ocb+r
//   mat0: bf16_hi(w) for both parities ; mat1: par==0 ? bf16_lo(w) : 0
// ---------------------------------------------------------------------------
__global__ void wblob_kernel(const float* __restrict__ w, __nv_bfloat16* __restrict__ blob,
                             int Cin, int nCh)
{
    int total = 2 * nCh * 2 * 8192;
    int idx = blockIdx.x * blockDim.x + threadIdx.x;
    if (idx >= total) return;
    int tile = idx >> 13;
    int e    = idx & 8191;
    int r = e >> 6;
    int q = e & 63;
    int mat = tile & 1;
    int tmp = tile >> 1;
    int c   = tmp % nCh;
    int ocb = tmp / nCh;
    int k2  = c * 64 + q;
    int k   = k2 >> 1;
    int par = k2 & 1;
    int cin = k >> 4;
    int tap = k & 15;
    int oc  = ocb * 128 + r;
    float v = w[((size_t)(oc * Cin + cin) << 4) + tap];
    __nv_bfloat16 h = __float2bfloat16(v);
    __nv_bfloat16 outv;
    if (mat == 0) outv = h;
    else          outv = par ? __float2bfloat16(0.0f)
                             : __float2bfloat16(v - __bfloat162float(h));
    u32 sw = swz128((u32)(r * 128 + q * 2));
    blob[(size_t)tile * 8192 + (sw >> 1)] = outv;
}

// ---------------------------------------------------------------------------
// conv1: fp32 implicit GEMM (Cin=3) with f32x2, epilogue packs hi/lo bf16 pair.
// ---------------------------------------------------------------------------
__global__ __launch_bounds__(256, 2)
void conv1_kernel(const float* __restrict__ x, const float* __restrict__ wT,
                  const float* __restrict__ bias, u32* __restrict__ y2,
                  int Cin, int Cout, int Hin, int Win, int Hout, int Wout)
{
    __shared__ float sA[2][16][128];
    __shared__ float sB[2][16][128];

    const int t  = threadIdx.x;
    const int tx = t & 15;
    const int ty = t >> 4;
    const int pxBase = blockIdx.x * 128;
    const int ocBase = blockIdx.y * 128;
    const int b = blockIdx.z;

    const int p_loc   = t & 127;
    const int tapHalf = t >> 7;
    const int p_glob  = pxBase + p_loc;
    const int oh = p_glob / Wout;
    const int ow = p_glob - oh * Wout;
    const int ih0 = 2 * oh - 1;
    const int iw0 = 2 * ow - 1;

    const float* xb = x + (size_t)b * Cin * Hin * Win;

    ull accp[8][4];
#pragma unroll
    for (int i = 0; i < 8; ++i)
#pragma unroll
        for (int j = 0; j < 4; ++j) accp[i][j] = 0ull;

    auto stage = [&](int buf, int cin) {
#pragma unroll
        for (int j = 0; j < 2; ++j) {
            int f   = t * 2 + j;
            int tap = f >> 5;
            int c4  = f & 31;
            cp16(&sA[buf][tap][c4 * 4], wT + ((size_t)(cin * 16 + tap) * Cout + ocBase + c4 * 4));
        }
        const float* xc = xb + (size_t)cin * Hin * Win;
#pragma unroll
        for (int i = 0; i < 8; ++i) {
            int tap = 2 * i + tapHalf;
            int kh = tap >> 2, kw = tap & 3;
            int ih = ih0 + kh;
            int iw = iw0 + kw;
            bool ok = (unsigned)ih < (unsigned)Hin && (unsigned)iw < (unsigned)Win;
            cp4z(&sB[buf][tap][p_loc], ok ? (xc + ih * Win + iw) : xc, ok ? 4 : 0);
        }
    };

    stage(0, 0);
    cp_commit();

    for (int cin = 0; cin < Cin; ++cin) {
        const int buf = cin & 1;
        if (cin + 1 < Cin) { stage(buf ^ 1, cin + 1); cp_commit(); cp_wait<1>(); }
        else               { cp_wait<0>(); }
        __syncthreads();
#pragma unroll
        for (int kk = 0; kk < 16; ++kk) {
            float4 a0 = *reinterpret_cast<const float4*>(&sA[buf][kk][ty * 4]);
            float4 a1 = *reinterpret_cast<const float4*>(&sA[buf][kk][64 + ty * 4]);
            ulonglong2 bq0 = *reinterpret_cast<const ulonglong2*>(&sB[buf][kk][tx * 4]);
            ulonglong2 bq1 = *reinterpret_cast<const ulonglong2*>(&sB[buf][kk][64 + tx * 4]);
            ull bp[4] = {bq0.x, bq0.y, bq1.x, bq1.y};
            float ar[8] = {a0.x, a0.y, a0.z, a0.w, a1.x, a1.y, a1.z, a1.w};
#pragma unroll
            for (int i = 0; i < 8; ++i) {
                ull ad = pack2(ar[i], ar[i]);
#pragma unroll
                for (int jp = 0; jp < 4; ++jp) accp[i][jp] = fma2(ad, bp[jp], accp[i][jp]);
            }
        }
        __syncthreads();
    }

    const int hw = Hout * Wout;
#pragma unroll
    for (int i = 0; i < 8; ++i) {
        int ocl = (i < 4) ? (ty * 4 + i) : (64 + ty * 4 + (i - 4));
        int oc  = ocBase + ocl;
        float bv = bias[oc];
        u32* yo = y2 + (size_t)(b * Cout + oc) * hw + pxBase;
        float2 p0 = unpack2(accp[i][0]);
        float2 p1 = unpack2(accp[i][1]);
        float2 p2 = unpack2(accp[i][2]);
        float2 p3 = unpack2(accp[i][3]);
        uint4 o0, o1;
        o0.x = pack_x2(silu_f(p0.x + bv));
        o0.y = pack_x2(silu_f(p0.y + bv));
        o0.z = pack_x2(silu_f(p1.x + bv));
        o0.w = pack_x2(silu_f(p1.y + bv));
        o1.x = pack_x2(silu_f(p2.x + bv));
        o1.y = pack_x2(silu_f(p2.y + bv));
        o1.z = pack_x2(silu_f(p3.x + bv));
        o1.w = pack_x2(silu_f(p3.y + bv));
        *reinterpret_cast<uint4*>(yo + tx * 4)      = o0;
        *reinterpret_cast<uint4*>(yo + 64 + tx * 4) = o1;
    }
}

// ---------------------------------------------------------------------------
// mma.sync conv (layers 2,3): split-bf16 hi/lo interleaved K on the tensor pipe.
// Block tile M=128 oc x N=128 px; 8 warps as 2(M)x4(N); per warp 64x32,
// 16 m16n8k16 tiles, fp32 register accumulators.
// smem per buffer: A_hi|A_lo (32KB, linear copy of pre-swizzled blob) +
//                  B (16KB, im2col cp4z into SW128 rows). Double buffered.
// ---------------------------------------------------------------------------
#define CMMA_BUF  49152
#define CMMA_SMEM (2 * CMMA_BUF + 1024)

template<int OUT_X2>
__global__ __launch_bounds__(256)
void conv_mma_kernel(const u32* __restrict__ x2, const __nv_bfloat16* __restrict__ blob,
                     const float* __restrict__ bias,
                     float* __restrict__ yF, u32* __restrict__ yX2,
                     int Cin, int Hin, int Win, int Hout, int Wout)
{
    extern __shared__ char smraw[];
    char* sm = (char*)(((size_t)smraw + 1023) & ~(size_t)1023);
    const u32 smb = smem_u32(sm);

    const int t   = threadIdx.x;
    const int wid = t >> 5;
    const int lid = t & 31;
    const int pxBase = blockIdx.x * 128;
    const int ocb    = blockIdx.y;
    const int b      = blockIdx.z;
    const int nCh    = Cin / 2;          // chunks of 64 k2 = 2 cins

    const int warpM = wid >> 2;          // 0..1 -> oc offset 64*warpM
    const int warpN = wid & 3;           // 0..3 -> px offset 32*warpN
    const int lrow  = lid & 7;
    const int msel  = lid >> 3;          // ldmatrix.x4 matrix select per lane

    // B staging coords
    const int p      = t & 127;
    const int jpar   = t >> 7;
    const int p_glob = pxBase + p;
    const int oh  = p_glob / Wout;
    const int ow  = p_glob - oh * Wout;
    const int ih0 = 2 * oh - 1;
    const int iw0 = 2 * ow - 1;

    float acc[4][4][4];
#pragma unroll
    for (int mi = 0; mi < 4; ++mi)
#pragma unroll
        for (int ni = 0; ni < 4; ++ni)
#pragma unroll
            for (int q = 0; q < 4; ++q) acc[mi][ni][q] = 0.0f;

    auto stage = [&](int buf, int c) {
        // A (32KB linear: hi tile then lo tile, both pre-swizzled)
        const char* srcA = (const char*)(blob + (size_t)((ocb * nCh + c) * 2) * 8192);
        char* dstA = sm + buf * CMMA_BUF;
#pragma unroll
        for (int k = 0; k < 8; ++k)
            cp16(dstA + (t + k * 256) * 16, srcA + (size_t)(t + k * 256) * 16);
        // B im2col (x2 elements, 4B each) into SW128 rows (row=px, 128B)
        char* dstB = sm + buf * CMMA_BUF + 32768;
        const int cinBase = 2 * c;
#pragma unroll
        for (int e = 0; e < 16; ++e) {
            int j   = jpar + 2 * e;        // u32 index in row, 0..31
            int cin = cinBase + (j >> 4);
            int tap = j & 15;
            int kh = tap >> 2, kw = tap & 3;
            int ih = ih0 + kh;
            int iw = iw0 + kw;
            bool ok = (unsigned)ih < (unsigned)Hin && (unsigned)iw < (unsigned)Win;
            const u32* src = x2 + ((size_t)(b * Cin + cin) * Hin + (ok ? ih : 0)) * Win + (ok ? iw : 0);
            cp4z(dstB + swz128((u32)(p * 128 + j * 4)), src, ok ? 4 : 0);
        }
    };

    stage(0, 0);
    cp_commit();

    for (int c = 0; c < nCh; ++c) {
        const int buf = c & 1;
        if (c + 1 < nCh) { stage(buf ^ 1, c + 1); cp_commit(); cp_wait<1>(); }
        else             { cp_wait<0>(); }
        __syncthreads();

        const u32 baseA  = smb + buf * CMMA_BUF;
        const u32 baseA2 = baseA + 16384;
        const u32 baseB  = smb + buf * CMMA_BUF + 32768;

#pragma unroll
        for (int kst = 0; kst < 4; ++kst) {
            const int kb = kst * 32;       // byte offset: 16 k2 per step

            // B fragments: 2 x ldmatrix.x4 covers 4 n8-tiles
            u32 bfr[4][2];
#pragma unroll
            for (int h = 0; h < 2; ++h) {
                int prow = warpN * 32 + h * 16 + ((msel >> 1) << 3) + lrow;
                int colb = kb + ((msel & 1) << 4);
                u32 addr = baseB + swz128((u32)(prow * 128 + colb));
                u32 r0, r1, r2, r3;
                ldmatrix_x4(r0, r1, r2, r3, addr);
                bfr[2 * h][0] = r0; bfr[2 * h][1] = r1;
                bfr[2 * h + 1][0] = r2; bfr[2 * h + 1][1] = r3;
            }

            // A fragments (hi and lo)
            u32 ah[4][4], al[4][4];
#pragma unroll
            for (int mi = 0; mi < 4; ++mi) {
                int arow = warpM * 64 + mi * 16 + ((msel & 1) << 3) + lrow;
                int colb = kb + ((msel >> 1) << 4);
                u32 off = swz128((u32)(arow * 128 + colb));
                ldmatrix_x4(ah[mi][0], ah[mi][1], ah[mi][2], ah[mi][3], baseA + off);
                ldmatrix_x4(al[mi][0], al[mi][1], al[mi][2], al[mi][3], baseA2 + off);
            }

#pragma unroll
            for (int mi = 0; mi < 4; ++mi)
#pragma unroll
                for (int ni = 0; ni < 4; ++ni) {
                    mma_bf16(acc[mi][ni], ah[mi], bfr[ni]);
                    mma_bf16(acc[mi][ni], al[mi], bfr[ni]);
                }
        }
        __syncthreads();
    }

    // ---- epilogue: bias + SiLU; acc layout c0,c1 -> (row g, col 2t,2t+1),
    //      c2,c3 -> (row g+8, same cols)
    const int g  = lid >> 2;
    const int tq = lid & 3;
    const int hw = Hout * Wout;
#pragma unroll
    for (int mi = 0; mi < 4; ++mi) {
        int oc0 = ocb * 128 + warpM * 64 + mi * 16 + g;
        float bv0 = bias[oc0];
        float bv1 = bias[oc0 + 8];
#pragma unroll
        for (int ni = 0; ni < 4; ++ni) {
            int px = pxBase + warpN * 32 + ni * 8 + 2 * tq;
            float v0 = silu_f(acc[mi][ni][0] + bv0);
            float v1 = silu_f(acc[mi][ni][1] + bv0);
            float v2 = silu_f(acc[mi][ni][2] + bv1);
            float v3 = silu_f(acc[mi][ni][3] + bv1);
            if (OUT_X2) {
                u32* y0 = yX2 + (size_t)(b * 256 + oc0) * hw + px;
                u32* y1 = yX2 + (size_t)(b * 256 + oc0 + 8) * hw + px;
                uint2 s0 = {pack_x2(v0), pack_x2(v1)};
                uint2 s1 = {pack_x2(v2), pack_x2(v3)};
                *reinterpret_cast<uint2*>(y0) = s0;
                *reinterpret_cast<uint2*>(y1) = s1;
            } else {
                float* y0 = yF + (size_t)(b * 256 + oc0) * hw + px;
                float* y1 = yF + (size_t)(b * 256 + oc0 + 8) * hw + px;
                float2 s0 = {v0, v1};
                float2 s1 = {v2, v3};
                *reinterpret_cast<float2*>(y0) = s0;
                *reinterpret_cast<float2*>(y1) = s1;
            }
        }
    }
}

// ---------------------------------------------------------------------------
// conv4: fp32 implicit GEMM
// ---------------------------------------------------------------------------
__global__ __launch_bounds__(256, 2)
void conv_silu_kernel(const float* __restrict__ x, const float* __restrict__ wT,
                      const float* __restrict__ bias, float* __restrict__ y,
                      int Cin, int Cout, int Hin, int Win, int Hout, int Wout)
{
    __shared__ float sA[2][16][128];
    __shared__ float sB[2][16][128];

    const int t  = threadIdx.x;
    const int tx = t & 15;
    const int ty = t >> 4;
    const int pxBase = blockIdx.x * 128;
    const int ocBase = blockIdx.y * 128;
    const int b = blockIdx.z;

    const int p_loc   = t & 127;
    const int tapHalf = t >> 7;
    const int p_glob  = pxBase + p_loc;
    const int oh = p_glob / Wout;
    const int ow = p_glob - oh * Wout;
    const int ih0 = 2 * oh - 1;
    const int iw0 = 2 * ow - 1;

    const float* xb = x + (size_t)b * Cin * Hin * Win;

    ull accp[8][4];
#pragma unroll
    for (int i = 0; i < 8; ++i)
#pragma unroll
        for (int j = 0; j < 4; ++j) accp[i][j] = 0ull;

    auto stage = [&](int buf, int cin) {
#pragma unroll
        for (int j = 0; j < 2; ++j) {
            int f   = t * 2 + j;
            int tap = f >> 5;
            int c4  = f & 31;
            cp16(&sA[buf][tap][c4 * 4], wT + ((size_t)(cin * 16 + tap) * Cout + ocBase + c4 * 4));
        }
        const float* xc = xb + (size_t)cin * Hin * Win;
#pragma unroll
        for (int i = 0; i < 8; ++i) {
            int tap = 2 * i + tapHalf;
            int kh = tap >> 2, kw = tap & 3;
            int ih = ih0 + kh;
            int iw = iw0 + kw;
            bool ok = (unsigned)ih < (unsigned)Hin && (unsigned)iw < (unsigned)Win;
            cp4z(&sB[buf][tap][p_loc], ok ? (xc + ih * Win + iw) : xc, ok ? 4 : 0);
        }
    };

    stage(0, 0);
    cp_commit();

    for (int cin = 0; cin < Cin; ++cin) {
        const int buf = cin & 1;
        if (cin + 1 < Cin) { stage(buf ^ 1, cin + 1); cp_commit(); cp_wait<1>(); }
        else               { cp_wait<0>(); }
        __syncthreads();
#pragma unroll
        for (int kk = 0; kk < 16; ++kk) {
            float4 a0 = *reinterpret_cast<const float4*>(&sA[buf][kk][ty * 4]);
            float4 a1 = *reinterpret_cast<const float4*>(&sA[buf][kk][64 + ty * 4]);
            ulonglong2 bq0 = *reinterpret_cast<const ulonglong2*>(&sB[buf][kk][tx * 4]);
            ulonglong2 bq1 = *reinterpret_cast<const ulonglong2*>(&sB[buf][kk][64 + tx * 4]);
            ull bp[4] = {bq0.x, bq0.y, bq1.x, bq1.y};
            float ar[8] = {a0.x, a0.y, a0.z, a0.w, a1.x, a1.y, a1.z, a1.w};
#pragma unroll
            for (int i = 0; i < 8; ++i) {
                ull ad = pack2(ar[i], ar[i]);
#pragma unroll
                for (int jp = 0; jp < 4; ++jp) accp[i][jp] = fma2(ad, bp[jp], accp[i][jp]);
            }
        }
        __syncthreads();
    }

    const int hw = Hout * Wout;
#pragma unroll
    for (int i = 0; i < 8; ++i) {
        int ocl = (i < 4) ? (ty * 4 + i) : (64 + ty * 4 + (i - 4));
        int oc  = ocBase + ocl;
        float bv = bias[oc];
        float* yo = y + (size_t)(b * Cout + oc) * hw + pxBase;
        float2 p0 = unpack2(accp[i][0]);
        float2 p1 = unpack2(accp[i][1]);
        float2 p2 = unpack2(accp[i][2]);
        float2 p3 = unpack2(accp[i][3]);
        float4 o0, o1;
        o0.x = silu_f(p0.x + bv);
        o0.y = silu_f(p0.y + bv);
        o0.z = silu_f(p1.x + bv);
        o0.w = silu_f(p1.y + bv);
        o1.x = silu_f(p2.x + bv);
        o1.y = silu_f(p2.y + bv);
        o1.z = silu_f(p3.x + bv);
        o1.w = silu_f(p3.y + bv);
        *reinterpret_cast<float4*>(yo + tx * 4)      = o0;
        *reinterpret_cast<float4*>(yo + 64 + tx * 4) = o1;
    }
}

// ---------------------------------------------------------------------------
// codebook squared norms
// ---------------------------------------------------------------------------
__global__ void cnorm_kernel(const float* __restrict__ cb, float* __restrict__ cn)
{
    int gwarp = (blockIdx.x * blockDim.x + threadIdx.x) >> 5;
    int lane  = threadIdx.x & 31;
    if (gwarp >= 8192) return;
    const float* p = cb + (size_t)gwarp * 256;
    float s = 0.0f;
#pragma unroll
    for (int i = 0; i < 8; ++i) { float v = p[lane + 32 * i]; s += v * v; }
#pragma unroll
    for (int o = 16; o > 0; o >>= 1) s += __shfl_xor_sync(0xFFFFFFFFu, s, o);
    if (lane == 0) cn[gwarp] = s;
}

// ---------------------------------------------------------------------------
// Fused VQ (fp32, f32x2)
// ---------------------------------------------------------------------------
__global__ __launch_bounds__(256)
void vq_kernel(const float* __restrict__ z, const float* __restrict__ cb,
               const float* __restrict__ cnorm,
               float* __restrict__ outQ, float* __restrict__ outIdx,
               int* __restrict__ idxOut)
{
    __shared__ float sZ[16][64];
    __shared__ float sC[16][256];
    __shared__ float zn[64];
    __shared__ float zpart[4][64];
    __shared__ float rmv[64][33];
    __shared__ int   rmi[64][33];
    __shared__ int   bidx[64];

    const int t = threadIdx.x;
    const int b = blockIdx.x >> 2;
    const int sBase = (blockIdx.x & 3) << 6;

    {
        int j = t & 63, dg = t >> 6;
        const float* zp = z + ((size_t)(b * 256 + dg * 64) << 8) + sBase + j;
        float s = 0.0f;
        for (int d = 0; d < 64; ++d) { float v = zp[(size_t)d << 8]; s += v * v; }
        zpart[dg][j] = s;
    }
    __syncthreads();
    if (t < 64) zn[t] = ((zpart[0][t] + zpart[1][t]) + zpart[2][t]) + zpart[3][t];
    __syncthreads();

    const int tx = t & 31;
    const int ty = t >> 5;

    int rl[8];
#pragma unroll
    for (int i = 0; i < 4; ++i) { rl[i] = ty * 4 + i; rl[4 + i] = 32 + ty * 4 + i; }
    float znr[8];
#pragma unroll
    for (int i = 0; i < 8; ++i) znr[i] = zn[rl[i]];

    float minv[8];
    int   mini[8];
#pragma unroll
    for (int i = 0; i < 8; ++i) { minv[i] = FLT_MAX; mini[i] = 0; }

    for (int ct = 0; ct < 32; ++ct) {
        ull dotp[8][4];
#pragma unroll
        for (int i = 0; i < 8; ++i)
#pragma unroll
            for (int j = 0; j < 4; ++j) dotp[i][j] = 0ull;

        for (int kc = 0; kc < 16; ++kc) {
            {
                int dd = t >> 4, j4 = (t & 15) << 2;
                float4 v = *reinterpret_cast<const float4*>(
                    z + ((size_t)(b * 256 + kc * 16 + dd) << 8) + sBase + j4);
                *reinterpret_cast<float4*>(&sZ[dd][j4]) = v;
            }
#pragma unroll
            for (int i2 = 0; i2 < 4; ++i2) {
                int f  = t + (i2 << 8);
                int cl = f >> 2;
                int dq = (f & 3) << 2;
                float4 v = *reinterpret_cast<const float4*>(
                    cb + ((size_t)(ct * 256 + cl) << 8) + kc * 16 + dq);
                sC[dq + 0][cl] = v.x;
                sC[dq + 1][cl] = v.y;
                sC[dq + 2][cl] = v.z;
                sC[dq + 3][cl] = v.w;
            }
            __syncthreads();
#pragma unroll
            for (int kk = 0; kk < 16; ++kk) {
                float4 a0 = *reinterpret_cast<const float4*>(&sZ[kk][ty * 4]);
                float4 a1 = *reinterpret_cast<const float4*>(&sZ[kk][32 + ty * 4]);
                ulonglong2 c0 = *reinterpret_cast<const ulonglong2*>(&sC[kk][tx * 4]);
                ulonglong2 c1 = *reinterpret_cast<const ulonglong2*>(&sC[kk][128 + tx * 4]);
                ull bp[4] = {c0.x, c0.y, c1.x, c1.y};
                float ar[8] = {a0.x, a0.y, a0.z, a0.w, a1.x, a1.y, a1.z, a1.w};
#pragma unroll
                for (int i = 0; i < 8; ++i) {
                    ull ad = pack2(ar[i], ar[i]);
#pragma unroll
                    for (int jp = 0; jp < 4; ++jp) dotp[i][jp] = fma2(ad, bp[jp], dotp[i][jp]);
                }
            }
            __syncthreads();
        }

        const int cbase = ct << 8;
#pragma unroll
        for (int i = 0; i < 8; ++i) {
            float2 q0 = unpack2(dotp[i][0]);
            float2 q1 = unpack2(dotp[i][1]);
            float2 q2 = unpack2(dotp[i][2]);
            float2 q3 = unpack2(dotp[i][3]);
            float dv[8] = {q0.x, q0.y, q1.x, q1.y, q2.x, q2.y, q3.x, q3.y};
#pragma unroll
            for (int j = 0; j < 8; ++j) {
                int code = cbase + ((j < 4) ? (tx * 4 + j) : (128 + tx * 4 + (j - 4)));
                float cn = cnorm[code];
                float d2 = __fadd_rn(__fsub_rn(znr[i], __fmul_rn(2.0f, dv[j])), cn);
                if (d2 < minv[i]) { minv[i] = d2; mini[i] = code; }
            }
        }
    }

#pragma unroll
    for (int i = 0; i < 8; ++i) { rmv[rl[i]][tx] = minv[i]; rmi[rl[i]][tx] = mini[i]; }
    __syncthreads();
    if (t < 64) {
        float bv = rmv[t][0];
        int   bi = rmi[t][0];
        for (int x2 = 1; x2 < 32; ++x2) {
            float v  = rmv[t][x2];
            int   ii = rmi[t][x2];
            if (v < bv || (v == bv && ii < bi)) { bv = v; bi = ii; }
        }
        bidx[t] = bi;
        int r = (b << 8) + sBase + t;
        outIdx[r] = (float)bi;
        idxOut[r] = bi;
    }
    __syncthreads();

    for (int i2 = 0; i2 < 64; ++i2) {
        int g = (i2 << 8) + t;
        int d = g >> 6;
        int j = g & 63;
        outQ[((size_t)(b * 256 + d) << 8) + sBase + j] = cb[((size_t)bidx[j] << 8) + d];
    }
}

// ---------------------------------------------------------------------------
// commit loss
// ---------------------------------------------------------------------------
__global__ void loss_partial_kernel(const float* __restrict__ z, const float* __restrict__ cb,
                                    const int* __restrict__ idx, float* __restrict__ part)
{
    __shared__ float sm[256];
    const int t = threadIdx.x;
    float s = 0.0f;
    for (int n = blockIdx.x * 256 + t; n < 32 * 256 * 256; n += 1024 * 256) {
        int b    = n >> 16;
        int d    = (n & 65535) >> 8;
        int sPos = n & 255;
        int r    = (b << 8) + sPos;
        float q  = cb[((size_t)idx[r] << 8) + d];
        float diff = z[n] - q;
        s += diff * diff;
    }
    sm[t] = s;
    __syncthreads();
    for (int o = 128; o > 0; o >>= 1) {
        if (t < o) sm[t] += sm[t + o];
        __syncthreads();
    }
    if (t == 0) part[blockIdx.x] = sm[0];
}

__global__ void loss_final_kernel(const float* __restrict__ part, float* __restrict__ out)
{
    __shared__ float sm[256];
    const int t = threadIdx.x;
    sm[t] = ((part[t] + part[t + 256]) + part[t + 512]) + part[t + 768];
    __syncthreads();
    for (int o = 128; o > 0; o >>= 1) {
        if (t < o) sm[t] += sm[t + o];
        __syncthreads();
    }
    if (t == 0) out[0] = sm[0] * (1.0f / 2097152.0f);
}

// ---------------------------------------------------------------------------
// launch
// ---------------------------------------------------------------------------
extern "C" void kernel_launch(void* const* d_in, const int* in_sizes, int n_in,
                              void* d_out, int out_size)
{
    const float* images = (const float*)d_in[0];
    const float* w1 = (const float*)d_in[1];
    const float* b1 = (const float*)d_in[2];
    const float* w2 = (const float*)d_in[3];
    const float* b2 = (const float*)d_in[4];
    const float* w3 = (const float*)d_in[5];
    const float* b3 = (const float*)d_in[6];
    const float* w4 = (const float*)d_in[7];
    const float* b4 = (const float*)d_in[8];
    const float* cb = (const float*)d_in[9];

    u32 *a1x2, *a2x2;
    float *a3, *a4, *cn, *lp, *w1T, *w4T;
    __nv_bfloat16 *w2b, *w3b;
    int* vidx;
    cudaGetSymbolAddress((void**)&a1x2, g_a1x2);
    cudaGetSymbolAddress((void**)&a2x2, g_a2x2);
    cudaGetSymbolAddress((void**)&a3, g_act3);
    cudaGetSymbolAddress((void**)&a4, g_act4);
    cudaGetSymbolAddress((void**)&cn, g_cnorm);
    cudaGetSymbolAddress((void**)&lp, g_lpart);
    cudaGetSymbolAddress((void**)&vidx, g_vqidx);
    cudaGetSymbolAddress((void**)&w1T, g_w1T);
    cudaGetSymbolAddress((void**)&w4T, g_w4T);
    cudaGetSymbolAddress((void**)&w2b, g_w2blob);
    cudaGetSymbolAddress((void**)&w3b, g_w3blob);

    float* out     = (float*)d_out;
    float* outQ    = out;
    float* outIdx  = out + 2097152;
    float* outLoss = out + 2105344;

    // >48KB dynamic smem opt-in (idempotent, host-side)
    cudaFuncSetAttribute(conv_mma_kernel<1>, cudaFuncAttributeMaxDynamicSharedMemorySize, CMMA_SMEM);
    cudaFuncSetAttribute(conv_mma_kernel<0>, cudaFuncAttributeMaxDynamicSharedMemorySize, CMMA_SMEM);

    // weight preps
    wtrans_kernel<<<(128 * 3 * 16 + 255) / 256, 256>>>(w1, w1T, 3, 128);
    wtrans_kernel<<<(256 * 256 * 16 + 255) / 256, 256>>>(w4, w4T, 256, 256);
    wblob_kernel<<<(2 * 64 * 2 * 8192 + 255) / 256, 256>>>(w2, w2b, 128, 64);
    wblob_kernel<<<(2 * 128 * 2 * 8192 + 255) / 256, 256>>>(w3, w3b, 256, 128);

    // Encoder
    conv1_kernel<<<dim3(128, 1, 32), 256>>>(images, w1T, b1, a1x2, 3, 128, 256, 256, 128, 128);
    conv_mma_kernel<1><<<dim3(32, 2, 32), 256, CMMA_SMEM>>>(a1x2, w2b, b2, nullptr, a2x2,
                                                            128, 128, 128, 64, 64);
    conv_mma_kernel<0><<<dim3(8, 2, 32), 256, CMMA_SMEM>>>(a2x2, w3b, b3, a3, nullptr,
                                                           256, 64, 64, 32, 32);
    conv_silu_kernel<<<dim3(2, 2, 32), 256>>>(a3, w4T, b4, a4, 256, 256, 32, 32, 16, 16);

    // VQ
    cnorm_kernel<<<1024, 256>>>(cb, cn);
    vq_kernel<<<128, 256>>>(a4, cb, cn, outQ, outIdx, vidx);

    // commit loss
    loss_partial_kernel<<<1024, 256>>>(a4, cb, vidx, lp);
    loss_final_kernel<<<1, 256>>>(lp, outLoss);
}